// round 2
// baseline (speedup 1.0000x reference)
#include <cuda_runtime.h>
#include <cstdint>

#define E_ACT 4
#define T_TOK 4096
#define D_DIM 1024
#define H_DIM 5632
#define CAP   4096

// ---------------- scratch (static device globals; no allocation) ----------------
__device__ int   g_counts[E_ACT];
__device__ int   g_tok[E_ACT * CAP];
__device__ float g_wgt[E_ACT * CAP];
__device__ int   g_rows[T_TOK * 2];
__device__ float g_h[(size_t)E_ACT * CAP * H_DIM];   // SwiGLU activations (369 MB cap)
__device__ float g_y[(size_t)E_ACT * CAP * D_DIM];   // per-(token,expert) scaled outputs

// ---------------- helpers ----------------
__device__ __forceinline__ uint32_t f2tf(float f) {
    uint32_t r;
    asm("cvt.rna.tf32.f32 %0, %1;" : "=r"(r) : "f"(f));
    return r;
}

__device__ __forceinline__ void mma_tf32(float c[4], const uint32_t a[4], const uint32_t b[2]) {
    asm volatile(
        "mma.sync.aligned.m16n8k8.row.col.f32.tf32.tf32.f32 "
        "{%0,%1,%2,%3}, {%4,%5,%6,%7}, {%8,%9}, {%0,%1,%2,%3};\n"
        : "+f"(c[0]), "+f"(c[1]), "+f"(c[2]), "+f"(c[3])
        : "r"(a[0]), "r"(a[1]), "r"(a[2]), "r"(a[3]), "r"(b[0]), "r"(b[1]));
}

// ---------------- kernel 0: reset routing counters ----------------
__global__ void zero_counts_kernel() {
    if (threadIdx.x < E_ACT) g_counts[threadIdx.x] = 0;
}

// ---------------- kernel 1: gate + route (1 warp per token) ----------------
__global__ __launch_bounds__(256) void gate_kernel(const float* __restrict__ x,
                                                   const float* __restrict__ gate_w) {
    __shared__ float gws[E_ACT][D_DIM];
    int tid = threadIdx.x;
    for (int i = tid * 4; i < E_ACT * D_DIM; i += 256 * 4) {
        *(float4*)&gws[0][i] = *(const float4*)&gate_w[i];   // rows 0..3 only
    }
    __syncthreads();

    int warp = tid >> 5, lane = tid & 31;
    int t = blockIdx.x * 8 + warp;
    const float* xp = x + (size_t)t * D_DIM;

    float a0 = 0.f, a1 = 0.f, a2 = 0.f, a3 = 0.f;
    for (int i = lane; i < D_DIM; i += 32) {
        float xv = xp[i];
        a0 += xv * gws[0][i];
        a1 += xv * gws[1][i];
        a2 += xv * gws[2][i];
        a3 += xv * gws[3][i];
    }
#pragma unroll
    for (int off = 16; off; off >>= 1) {
        a0 += __shfl_xor_sync(0xffffffffu, a0, off);
        a1 += __shfl_xor_sync(0xffffffffu, a1, off);
        a2 += __shfl_xor_sync(0xffffffffu, a2, off);
        a3 += __shfl_xor_sync(0xffffffffu, a3, off);
    }

    if (lane == 0) {
        float l[4] = {a0, a1, a2, a3};
        int b0 = 0;
#pragma unroll
        for (int e2 = 1; e2 < 4; e2++) if (l[e2] > l[b0]) b0 = e2;   // stable argmax
        int b1 = (b0 == 0) ? 1 : 0;
#pragma unroll
        for (int e2 = 0; e2 < 4; e2++) if (e2 != b0 && l[e2] > l[b1]) b1 = e2;

        float wa = 1.0f / (1.0f + expf(l[b1] - l[b0]));  // renormalized top-2 softmax
        float wb = 1.0f - wa;

        int p0 = atomicAdd(&g_counts[b0], 1);
        g_tok[b0 * CAP + p0] = t;
        g_wgt[b0 * CAP + p0] = wa;
        g_rows[t * 2 + 0] = b0 * CAP + p0;

        int p1 = atomicAdd(&g_counts[b1], 1);
        g_tok[b1 * CAP + p1] = t;
        g_wgt[b1 * CAP + p1] = wb;
        g_rows[t * 2 + 1] = b1 * CAP + p1;
    }
}

// ---------------- kernel 2: grouped GEMM  h = silu(X@W1) * (X@W3) ----------------
// grid (H/64, CAP/128, E_ACT), 256 threads, 128x64 tile for BOTH w1 and w3.
__global__ __launch_bounds__(256) void pass1_kernel(const float* __restrict__ x,
                                                    const float* __restrict__ w1,
                                                    const float* __restrict__ w3) {
    int e = blockIdx.z;
    int Ne = g_counts[e];
    int m0 = blockIdx.y * 128;
    if (m0 >= Ne) return;
    int n0 = blockIdx.x * 64;

    __shared__ float Xs[128][36];
    __shared__ float W1s[32][68];
    __shared__ float W3s[32][68];
    __shared__ int   toks[128];

    int tid = threadIdx.x;
    if (tid < 128) {
        int r = m0 + tid;
        toks[tid] = g_tok[e * CAP + (r < Ne ? r : 0)];   // clamp padding rows to a valid token
    }
    __syncthreads();

    int warp = tid >> 5, lane = tid & 31;
    int wm = warp >> 1, wn = warp & 1;        // 4x2 warp grid: 32x32 per warp per matrix
    int g = lane >> 2, tg = lane & 3;

    float c1[2][4][4], c3[2][4][4];
#pragma unroll
    for (int mi = 0; mi < 2; mi++)
#pragma unroll
        for (int ni = 0; ni < 4; ni++)
#pragma unroll
            for (int r = 0; r < 4; r++) { c1[mi][ni][r] = 0.f; c3[mi][ni][r] = 0.f; }

    int xr = tid >> 3, xc = (tid & 7) * 4;    // X loader: rows xr+32i, float4 col xc
    int wr = tid >> 4, wc = (tid & 15) * 4;   // W loader: rows wr+16i, float4 col wc

    for (int k0 = 0; k0 < D_DIM; k0 += 32) {
#pragma unroll
        for (int i = 0; i < 4; i++) {
            int row = xr + 32 * i;
            *(float4*)&Xs[row][xc] =
                *(const float4*)(x + (size_t)toks[row] * D_DIM + k0 + xc);
        }
#pragma unroll
        for (int i = 0; i < 2; i++) {
            int kr = wr + 16 * i;
            size_t off = ((size_t)e * D_DIM + k0 + kr) * H_DIM + n0 + wc;
            *(float4*)&W1s[kr][wc] = *(const float4*)(w1 + off);
            *(float4*)&W3s[kr][wc] = *(const float4*)(w3 + off);
        }
        __syncthreads();

#pragma unroll
        for (int k8 = 0; k8 < 32; k8 += 8) {
            uint32_t a[2][4];
#pragma unroll
            for (int mi = 0; mi < 2; mi++) {
                int rb = wm * 32 + mi * 16;
                a[mi][0] = f2tf(Xs[rb + g][k8 + tg]);
                a[mi][1] = f2tf(Xs[rb + g + 8][k8 + tg]);
                a[mi][2] = f2tf(Xs[rb + g][k8 + tg + 4]);
                a[mi][3] = f2tf(Xs[rb + g + 8][k8 + tg + 4]);
            }
#pragma unroll
            for (int ni = 0; ni < 4; ni++) {
                int col = wn * 32 + ni * 8 + g;
                uint32_t b1f[2], b3f[2];
                b1f[0] = f2tf(W1s[k8 + tg][col]);
                b1f[1] = f2tf(W1s[k8 + tg + 4][col]);
                b3f[0] = f2tf(W3s[k8 + tg][col]);
                b3f[1] = f2tf(W3s[k8 + tg + 4][col]);
#pragma unroll
                for (int mi = 0; mi < 2; mi++) {
                    mma_tf32(c1[mi][ni], a[mi], b1f);
                    mma_tf32(c3[mi][ni], a[mi], b3f);
                }
            }
        }
        __syncthreads();
    }

    // epilogue: SwiGLU, write fp32 h
#pragma unroll
    for (int mi = 0; mi < 2; mi++) {
#pragma unroll
        for (int hi = 0; hi < 2; hi++) {
            int row = m0 + wm * 32 + mi * 16 + g + hi * 8;
            if (row < Ne) {
                size_t base = ((size_t)e * CAP + row) * H_DIM + n0 + wn * 32;
#pragma unroll
                for (int ni = 0; ni < 4; ni++) {
                    float v1a = c1[mi][ni][hi * 2 + 0], v1b = c1[mi][ni][hi * 2 + 1];
                    float v3a = c3[mi][ni][hi * 2 + 0], v3b = c3[mi][ni][hi * 2 + 1];
                    float2 hv;
                    hv.x = (v1a / (1.f + expf(-v1a))) * v3a;
                    hv.y = (v1b / (1.f + expf(-v1b))) * v3b;
                    *(float2*)&g_h[base + ni * 8 + 2 * tg] = hv;
                }
            }
        }
    }
}

// ---------------- kernel 3: grouped GEMM  y = (h @ W2) * gate_weight ----------------
// grid (D/128, CAP/128, E_ACT), 256 threads, 128x128 tile.
__global__ __launch_bounds__(256) void pass2_kernel(const float* __restrict__ w2) {
    int e = blockIdx.z;
    int Ne = g_counts[e];
    int m0 = blockIdx.y * 128;
    if (m0 >= Ne) return;
    int n0 = blockIdx.x * 128;

    __shared__ float Hs[128][36];
    __shared__ float Ws[32][132];

    int tid = threadIdx.x;
    int warp = tid >> 5, lane = tid & 31;
    int wm = warp >> 1, wn = warp & 1;        // warp tile 32x64
    int g = lane >> 2, tg = lane & 3;

    float cc[2][8][4];
#pragma unroll
    for (int mi = 0; mi < 2; mi++)
#pragma unroll
        for (int ni = 0; ni < 8; ni++)
#pragma unroll
            for (int r = 0; r < 4; r++) cc[mi][ni][r] = 0.f;

    int xr = tid >> 3, xc = (tid & 7) * 4;
    int wr = tid >> 5, wc = (tid & 31) * 4;

    const float* hbase = g_h + ((size_t)e * CAP + m0) * H_DIM;

    for (int k0 = 0; k0 < H_DIM; k0 += 32) {
#pragma unroll
        for (int i = 0; i < 4; i++) {
            int row = xr + 32 * i;
            *(float4*)&Hs[row][xc] =
                *(const float4*)(hbase + (size_t)row * H_DIM + k0 + xc);
        }
#pragma unroll
        for (int i = 0; i < 4; i++) {
            int kr = wr + 8 * i;
            *(float4*)&Ws[kr][wc] =
                *(const float4*)(w2 + ((size_t)e * H_DIM + k0 + kr) * D_DIM + n0 + wc);
        }
        __syncthreads();

#pragma unroll
        for (int k8 = 0; k8 < 32; k8 += 8) {
            uint32_t a[2][4];
#pragma unroll
            for (int mi = 0; mi < 2; mi++) {
                int rb = wm * 32 + mi * 16;
                a[mi][0] = f2tf(Hs[rb + g][k8 + tg]);
                a[mi][1] = f2tf(Hs[rb + g + 8][k8 + tg]);
                a[mi][2] = f2tf(Hs[rb + g][k8 + tg + 4]);
                a[mi][3] = f2tf(Hs[rb + g + 8][k8 + tg + 4]);
            }
#pragma unroll
            for (int ni = 0; ni < 8; ni++) {
                int col = wn * 64 + ni * 8 + g;
                uint32_t b[2];
                b[0] = f2tf(Ws[k8 + tg][col]);
                b[1] = f2tf(Ws[k8 + tg + 4][col]);
#pragma unroll
                for (int mi = 0; mi < 2; mi++) mma_tf32(cc[mi][ni], a[mi], b);
            }
        }
        __syncthreads();
    }

#pragma unroll
    for (int mi = 0; mi < 2; mi++) {
#pragma unroll
        for (int hi = 0; hi < 2; hi++) {
            int row = m0 + wm * 32 + mi * 16 + g + hi * 8;
            if (row < Ne) {
                float wrow = g_wgt[e * CAP + row];
                size_t base = ((size_t)e * CAP + row) * D_DIM + n0 + wn * 64;
#pragma unroll
                for (int ni = 0; ni < 8; ni++) {
                    float2 v;
                    v.x = cc[mi][ni][hi * 2 + 0] * wrow;
                    v.y = cc[mi][ni][hi * 2 + 1] * wrow;
                    *(float2*)&g_y[base + ni * 8 + 2 * tg] = v;
                }
            }
        }
    }
}

// ---------------- kernel 4: deterministic combine  out[t] = y[rowA] + y[rowB] ----------------
__global__ void combine_kernel(float* __restrict__ out) {
    int idx = blockIdx.x * blockDim.x + threadIdx.x;   // float4 index, T*D/4 total
    int t = idx >> 8;                                  // 256 float4 per token row
    int c = (idx & 255) * 4;
    int rA = g_rows[t * 2 + 0];
    int rB = g_rows[t * 2 + 1];
    float4 a = *(const float4*)&g_y[(size_t)rA * D_DIM + c];
    float4 b = *(const float4*)&g_y[(size_t)rB * D_DIM + c];
    float4 o;
    o.x = a.x + b.x; o.y = a.y + b.y; o.z = a.z + b.z; o.w = a.w + b.w;
    *(float4*)&out[(size_t)t * D_DIM + c] = o;
}

// ---------------- launch ----------------
extern "C" void kernel_launch(void* const* d_in, const int* in_sizes, int n_in,
                              void* d_out, int out_size) {
    const float* x      = (const float*)d_in[0];
    const float* gate_w = (const float*)d_in[1];
    const float* w1     = (const float*)d_in[2];
    const float* w2     = (const float*)d_in[3];
    const float* w3     = (const float*)d_in[4];
    float* out = (float*)d_out;

    zero_counts_kernel<<<1, 32>>>();
    gate_kernel<<<T_TOK / 8, 256>>>(x, gate_w);
    pass1_kernel<<<dim3(H_DIM / 64, CAP / 128, E_ACT), 256>>>(x, w1, w3);
    pass2_kernel<<<dim3(D_DIM / 128, CAP / 128, E_ACT), 256>>>(w2);
    combine_kernel<<<(T_TOK * D_DIM / 4) / 256, 256>>>(out);
}

// round 6
// speedup vs baseline: 1.2375x; 1.2375x over previous
#include <cuda_runtime.h>
#include <cstdint>

#define E_ACT 4
#define T_TOK 4096
#define D_DIM 1024
#define H_DIM 5632
#define CAP   4096
#define BK    16

// ---------------- scratch (static device globals; no allocation) ----------------
__device__ int   g_counts[E_ACT];
__device__ int   g_tok[E_ACT * CAP];
__device__ float g_wgt[E_ACT * CAP];
__device__ int   g_rows[T_TOK * 2];
__device__ float g_h[(size_t)E_ACT * CAP * H_DIM];   // SwiGLU activations
__device__ float g_y[(size_t)E_ACT * CAP * D_DIM];   // per-(token,expert) scaled outputs

// ---------------- helpers ----------------
__device__ __forceinline__ uint32_t f2tf(float f) {
    uint32_t r;
    asm("cvt.rna.tf32.f32 %0, %1;" : "=r"(r) : "f"(f));
    return r;
}

__device__ __forceinline__ void mma_tf32(float c[4], const uint32_t a[4], const uint32_t b[2]) {
    asm volatile(
        "mma.sync.aligned.m16n8k8.row.col.f32.tf32.tf32.f32 "
        "{%0,%1,%2,%3}, {%4,%5,%6,%7}, {%8,%9}, {%0,%1,%2,%3};\n"
        : "+f"(c[0]), "+f"(c[1]), "+f"(c[2]), "+f"(c[3])
        : "r"(a[0]), "r"(a[1]), "r"(a[2]), "r"(a[3]), "r"(b[0]), "r"(b[1]));
}

__device__ __forceinline__ void cp_async16(void* smem, const void* gmem) {
    uint32_t s = (uint32_t)__cvta_generic_to_shared(smem);
    asm volatile("cp.async.cg.shared.global [%0], [%1], 16;\n" :: "r"(s), "l"(gmem));
}
__device__ __forceinline__ void cp_commit() { asm volatile("cp.async.commit_group;\n"); }
template <int N>
__device__ __forceinline__ void cp_wait() { asm volatile("cp.async.wait_group %0;\n" :: "n"(N)); }

// ---------------- kernel 0: reset routing counters ----------------
__global__ void zero_counts_kernel() {
    if (threadIdx.x < E_ACT) g_counts[threadIdx.x] = 0;
}

// ---------------- kernel 1: gate + route (1 warp per token) ----------------
__global__ __launch_bounds__(256) void gate_kernel(const float* __restrict__ x,
                                                   const float* __restrict__ gate_w) {
    __shared__ float gws[E_ACT][D_DIM];
    int tid = threadIdx.x;
    for (int i = tid * 4; i < E_ACT * D_DIM; i += 256 * 4) {
        *(float4*)&gws[0][i] = *(const float4*)&gate_w[i];   // rows 0..3 only
    }
    __syncthreads();

    int warp = tid >> 5, lane = tid & 31;
    int t = blockIdx.x * 8 + warp;
    const float* xp = x + (size_t)t * D_DIM;

    float a0 = 0.f, a1 = 0.f, a2 = 0.f, a3 = 0.f;
    for (int i = lane; i < D_DIM; i += 32) {
        float xv = xp[i];
        a0 += xv * gws[0][i];
        a1 += xv * gws[1][i];
        a2 += xv * gws[2][i];
        a3 += xv * gws[3][i];
    }
#pragma unroll
    for (int off = 16; off; off >>= 1) {
        a0 += __shfl_xor_sync(0xffffffffu, a0, off);
        a1 += __shfl_xor_sync(0xffffffffu, a1, off);
        a2 += __shfl_xor_sync(0xffffffffu, a2, off);
        a3 += __shfl_xor_sync(0xffffffffu, a3, off);
    }

    if (lane == 0) {
        float l[4] = {a0, a1, a2, a3};
        int b0 = 0;
#pragma unroll
        for (int e2 = 1; e2 < 4; e2++) if (l[e2] > l[b0]) b0 = e2;   // stable argmax
        int b1 = (b0 == 0) ? 1 : 0;
#pragma unroll
        for (int e2 = 0; e2 < 4; e2++) if (e2 != b0 && l[e2] > l[b1]) b1 = e2;

        float wa = 1.0f / (1.0f + expf(l[b1] - l[b0]));  // renormalized top-2 softmax
        float wb = 1.0f - wa;

        int p0 = atomicAdd(&g_counts[b0], 1);
        g_tok[b0 * CAP + p0] = t;
        g_wgt[b0 * CAP + p0] = wa;
        g_rows[t * 2 + 0] = b0 * CAP + p0;

        int p1 = atomicAdd(&g_counts[b1], 1);
        g_tok[b1 * CAP + p1] = t;
        g_wgt[b1 * CAP + p1] = wb;
        g_rows[t * 2 + 1] = b1 * CAP + p1;
    }
}

// ---------------- kernel 2: grouped GEMM  h = silu(X@W1) * (X@W3) ----------------
// grid (H/64, CAP/128, E_ACT), 256 threads, 128x64 tile for BOTH w1 and w3.
// 3-stage cp.async pipeline over BK=16 k-slices, single __syncthreads per slice.
// Invariant: one commit_group per iteration (empty past the end), so at iter i
// the last committed group is stage i+1 and wait_group<1> guarantees stage i landed.
struct P1Smem {
    float Xs[3][128][20];   // pad 4: a-load banks 20g+tg -> conflict-free
    float W1[3][BK][72];    // pad to 72 (=8 mod 32): b-load banks 8tg+g -> conflict-free
    float W3[3][BK][72];
    int   toks[128];
};

__global__ __launch_bounds__(256) void pass1_kernel(const float* __restrict__ x,
                                                    const float* __restrict__ w1,
                                                    const float* __restrict__ w3) {
    extern __shared__ char smem_raw[];
    P1Smem* sm = (P1Smem*)smem_raw;

    int e = blockIdx.z;
    int Ne = g_counts[e];
    int m0 = blockIdx.y * 128;
    if (m0 >= Ne) return;
    int n0 = blockIdx.x * 64;

    int tid = threadIdx.x;
    if (tid < 128) {
        int r = m0 + tid;
        sm->toks[tid] = g_tok[e * CAP + (r < Ne ? r : 0)];
    }
    __syncthreads();

    // per-thread loader geometry (constant across stages)
    int xrow = tid >> 2;              // 0..63 (+64 for second chunk)
    int xcol = (tid & 3) * 4;         // 0,4,8,12
    const float* xg0 = x + (size_t)sm->toks[xrow] * D_DIM + xcol;
    const float* xg1 = x + (size_t)sm->toks[xrow + 64] * D_DIM + xcol;
    int wr = tid >> 4;                // 0..15
    int wc = (tid & 15) * 4;          // 0..60
    const float* w1g = w1 + ((size_t)e * D_DIM + wr) * H_DIM + n0 + wc;
    const float* w3g = w3 + ((size_t)e * D_DIM + wr) * H_DIM + n0 + wc;

    auto load_stage = [&](int s) {
        int buf = s % 3;
        int k0 = s * BK;
        cp_async16(&sm->Xs[buf][xrow][xcol],      xg0 + k0);
        cp_async16(&sm->Xs[buf][xrow + 64][xcol], xg1 + k0);
        cp_async16(&sm->W1[buf][wr][wc], w1g + (size_t)k0 * H_DIM);
        cp_async16(&sm->W3[buf][wr][wc], w3g + (size_t)k0 * H_DIM);
        cp_commit();
    };

    int warp = tid >> 5, lane = tid & 31;
    int wm = warp >> 1, wn = warp & 1;        // 4x2 warp grid: 32x32 per warp per matrix
    int g = lane >> 2, tg = lane & 3;

    float c1[2][4][4], c3[2][4][4];
#pragma unroll
    for (int mi = 0; mi < 2; mi++)
#pragma unroll
        for (int ni = 0; ni < 4; ni++)
#pragma unroll
            for (int r = 0; r < 4; r++) { c1[mi][ni][r] = 0.f; c3[mi][ni][r] = 0.f; }

    const int NK = D_DIM / BK;   // 64
    load_stage(0);
    load_stage(1);

    for (int i = 0; i < NK; i++) {
        cp_wait<1>();            // last committed group is stage i+1 -> stage i landed
        __syncthreads();         // all warps done with stage i-1's buffer
        if (i + 2 < NK) load_stage(i + 2);   // writes buf (i-1)%3: safe
        else cp_commit();                    // empty group: keeps wait<1> tail-correct

        int buf = i % 3;
#pragma unroll
        for (int k8 = 0; k8 < BK; k8 += 8) {
            uint32_t a[2][4];
#pragma unroll
            for (int mi = 0; mi < 2; mi++) {
                int rb = wm * 32 + mi * 16;
                a[mi][0] = f2tf(sm->Xs[buf][rb + g][k8 + tg]);
                a[mi][1] = f2tf(sm->Xs[buf][rb + g + 8][k8 + tg]);
                a[mi][2] = f2tf(sm->Xs[buf][rb + g][k8 + tg + 4]);
                a[mi][3] = f2tf(sm->Xs[buf][rb + g + 8][k8 + tg + 4]);
            }
#pragma unroll
            for (int ni = 0; ni < 4; ni++) {
                int col = wn * 32 + ni * 8 + g;
                uint32_t b1f[2], b3f[2];
                b1f[0] = f2tf(sm->W1[buf][k8 + tg][col]);
                b1f[1] = f2tf(sm->W1[buf][k8 + tg + 4][col]);
                b3f[0] = f2tf(sm->W3[buf][k8 + tg][col]);
                b3f[1] = f2tf(sm->W3[buf][k8 + tg + 4][col]);
#pragma unroll
                for (int mi = 0; mi < 2; mi++) {
                    mma_tf32(c1[mi][ni], a[mi], b1f);
                    mma_tf32(c3[mi][ni], a[mi], b3f);
                }
            }
        }
    }

    // epilogue: SwiGLU, write fp32 h
#pragma unroll
    for (int mi = 0; mi < 2; mi++) {
#pragma unroll
        for (int hi = 0; hi < 2; hi++) {
            int row = m0 + wm * 32 + mi * 16 + g + hi * 8;
            if (row < Ne) {
                size_t base = ((size_t)e * CAP + row) * H_DIM + n0 + wn * 32;
#pragma unroll
                for (int ni = 0; ni < 4; ni++) {
                    float v1a = c1[mi][ni][hi * 2 + 0], v1b = c1[mi][ni][hi * 2 + 1];
                    float v3a = c3[mi][ni][hi * 2 + 0], v3b = c3[mi][ni][hi * 2 + 1];
                    float2 hv;
                    hv.x = (v1a / (1.f + expf(-v1a))) * v3a;
                    hv.y = (v1b / (1.f + expf(-v1b))) * v3b;
                    *(float2*)&g_h[base + ni * 8 + 2 * tg] = hv;
                }
            }
        }
    }
}

// ---------------- kernel 3: grouped GEMM  y = (h @ W2) * gate_weight ----------------
// grid (D/128, CAP/128, E_ACT), 256 threads, 128x128 tile, same 3-stage pipeline.
struct P2Smem {
    float Hs[3][128][20];
    float Ws[3][BK][136];   // 136 = 8 mod 32 -> conflict-free b loads
};

__global__ __launch_bounds__(256) void pass2_kernel(const float* __restrict__ w2) {
    extern __shared__ char smem_raw[];
    P2Smem* sm = (P2Smem*)smem_raw;

    int e = blockIdx.z;
    int Ne = g_counts[e];
    int m0 = blockIdx.y * 128;
    if (m0 >= Ne) return;
    int n0 = blockIdx.x * 128;

    int tid = threadIdx.x;
    int warp = tid >> 5, lane = tid & 31;
    int wm = warp >> 1, wn = warp & 1;        // warp tile 32x64
    int g = lane >> 2, tg = lane & 3;

    int xrow = tid >> 2;
    int xcol = (tid & 3) * 4;
    const float* hg0 = g_h + ((size_t)e * CAP + m0 + xrow) * H_DIM + xcol;
    const float* hg1 = g_h + ((size_t)e * CAP + m0 + xrow + 64) * H_DIM + xcol;
    int wr = tid >> 4;
    int wc = (tid & 15) * 4;
    const float* wg = w2 + ((size_t)e * H_DIM + wr) * D_DIM + n0 + wc;

    auto load_stage = [&](int s) {
        int buf = s % 3;
        int k0 = s * BK;
        cp_async16(&sm->Hs[buf][xrow][xcol],      hg0 + k0);
        cp_async16(&sm->Hs[buf][xrow + 64][xcol], hg1 + k0);
        cp_async16(&sm->Ws[buf][wr][wc],      wg + (size_t)k0 * D_DIM);
        cp_async16(&sm->Ws[buf][wr][wc + 64], wg + (size_t)k0 * D_DIM + 64);
        cp_commit();
    };

    float cc[2][8][4];
#pragma unroll
    for (int mi = 0; mi < 2; mi++)
#pragma unroll
        for (int ni = 0; ni < 8; ni++)
#pragma unroll
            for (int r = 0; r < 4; r++) cc[mi][ni][r] = 0.f;

    const int NK = H_DIM / BK;   // 352
    load_stage(0);
    load_stage(1);

    for (int i = 0; i < NK; i++) {
        cp_wait<1>();
        __syncthreads();
        if (i + 2 < NK) load_stage(i + 2);
        else cp_commit();                    // empty group: tail correctness

        int buf = i % 3;
#pragma unroll
        for (int k8 = 0; k8 < BK; k8 += 8) {
            uint32_t a[2][4];
#pragma unroll
            for (int mi = 0; mi < 2; mi++) {
                int rb = wm * 32 + mi * 16;
                a[mi][0] = f2tf(sm->Hs[buf][rb + g][k8 + tg]);
                a[mi][1] = f2tf(sm->Hs[buf][rb + g + 8][k8 + tg]);
                a[mi][2] = f2tf(sm->Hs[buf][rb + g][k8 + tg + 4]);
                a[mi][3] = f2tf(sm->Hs[buf][rb + g + 8][k8 + tg + 4]);
            }
#pragma unroll
            for (int ni = 0; ni < 8; ni++) {
                int col = wn * 64 + ni * 8 + g;
                uint32_t b[2];
                b[0] = f2tf(sm->Ws[buf][k8 + tg][col]);
                b[1] = f2tf(sm->Ws[buf][k8 + tg + 4][col]);
#pragma unroll
                for (int mi = 0; mi < 2; mi++) mma_tf32(cc[mi][ni], a[mi], b);
            }
        }
    }

#pragma unroll
    for (int mi = 0; mi < 2; mi++) {
#pragma unroll
        for (int hi = 0; hi < 2; hi++) {
            int row = m0 + wm * 32 + mi * 16 + g + hi * 8;
            if (row < Ne) {
                float wrow = g_wgt[e * CAP + row];
                size_t base = ((size_t)e * CAP + row) * D_DIM + n0 + wn * 64;
#pragma unroll
                for (int ni = 0; ni < 8; ni++) {
                    float2 v;
                    v.x = cc[mi][ni][hi * 2 + 0] * wrow;
                    v.y = cc[mi][ni][hi * 2 + 1] * wrow;
                    *(float2*)&g_y[base + ni * 8 + 2 * tg] = v;
                }
            }
        }
    }
}

// ---------------- kernel 4: deterministic combine  out[t] = y[rowA] + y[rowB] ----------------
__global__ void combine_kernel(float* __restrict__ out) {
    int idx = blockIdx.x * blockDim.x + threadIdx.x;   // float4 index, T*D/4 total
    int t = idx >> 8;                                  // 256 float4 per token row
    int c = (idx & 255) * 4;
    int rA = g_rows[t * 2 + 0];
    int rB = g_rows[t * 2 + 1];
    float4 a = *(const float4*)&g_y[(size_t)rA * D_DIM + c];
    float4 b = *(const float4*)&g_y[(size_t)rB * D_DIM + c];
    float4 o;
    o.x = a.x + b.x; o.y = a.y + b.y; o.z = a.z + b.z; o.w = a.w + b.w;
    *(float4*)&out[(size_t)t * D_DIM + c] = o;
}

// ---------------- launch ----------------
extern "C" void kernel_launch(void* const* d_in, const int* in_sizes, int n_in,
                              void* d_out, int out_size) {
    const float* x      = (const float*)d_in[0];
    const float* gate_w = (const float*)d_in[1];
    const float* w1     = (const float*)d_in[2];
    const float* w2     = (const float*)d_in[3];
    const float* w3     = (const float*)d_in[4];
    float* out = (float*)d_out;

    cudaFuncSetAttribute(pass1_kernel, cudaFuncAttributeMaxDynamicSharedMemorySize,
                         (int)sizeof(P1Smem));
    cudaFuncSetAttribute(pass2_kernel, cudaFuncAttributeMaxDynamicSharedMemorySize,
                         (int)sizeof(P2Smem));

    zero_counts_kernel<<<1, 32>>>();
    gate_kernel<<<T_TOK / 8, 256>>>(x, gate_w);
    pass1_kernel<<<dim3(H_DIM / 64, CAP / 128, E_ACT), 256, sizeof(P1Smem)>>>(x, w1, w3);
    pass2_kernel<<<dim3(D_DIM / 128, CAP / 128, E_ACT), 256, sizeof(P2Smem)>>>(w2);
    combine_kernel<<<(T_TOK * D_DIM / 4) / 256, 256>>>(out);
}